// round 2
// baseline (speedup 1.0000x reference)
#include <cuda_runtime.h>
#include <stdint.h>

#define NMAX 100000
#define EMAX 1600000

// ---------------- scratch (static device globals; no runtime allocation) ----------------
__device__ __align__(16) float g_qkv[NMAX * 384];    // q | k | v  per row
__device__ __align__(16) float g_ex[(size_t)EMAX * 8];
__device__ __align__(16) float g_denom[NMAX * 8];
__device__ __align__(16) float g_agg[NMAX * 128];
__device__ __align__(16) float g_h[NMAX * 128];
__device__ __align__(16) float g_hn[NMAX * 128];
__device__ __align__(16) float g_t2[NMAX * 64];

__device__ __forceinline__ void red_add_v4(float* p, float a, float b, float c, float d) {
    asm volatile("red.global.add.v4.f32 [%0], {%1,%2,%3,%4};"
                 :: "l"(p), "f"(a), "f"(b), "f"(c), "f"(d) : "memory");
}

__device__ __forceinline__ int clampi(int v, int hi) {
    return v < 0 ? 0 : (v >= hi ? hi - 1 : v);
}

// ---------------- zero-init denom + agg (graph replay must re-zero) ----------------
__global__ void zero_kernel(int n) {
    int i = blockIdx.x * blockDim.x + threadIdx.x;
    float4 z = {0.f, 0.f, 0.f, 0.f};
    int nd = n * 2;    // denom: n*8 floats = n*2 float4
    int na = n * 32;   // agg:   n*128 floats = n*32 float4
    if (i < nd) reinterpret_cast<float4*>(g_denom)[i] = z;
    if (i < na) reinterpret_cast<float4*>(g_agg)[i] = z;
}

// ---------------- generic K=128 sgemm: C[M,NCOLS] = A[M,128] @ B[128,NCOLS] (+bias)(+resid)(relu) ----
template<int NCOLS, bool BIAS, bool RESID, bool RELU>
__global__ __launch_bounds__(256)
void sgemm_k128(const float* __restrict__ A, const float* __restrict__ B,
                const float* __restrict__ bias, const float* __restrict__ resid,
                float* __restrict__ C, int M)
{
    __shared__ __align__(16) float As[16][64];
    __shared__ __align__(16) float Bs[16][64];

    const int t  = threadIdx.x;
    const int m0 = blockIdx.x * 64;
    const int n0 = blockIdx.y * 64;
    const int tx = t & 15;          // output col group
    const int ty = t >> 4;          // output row group
    const int arow = t >> 2;        // 0..63
    const int acol = (t & 3) << 2;  // 0,4,8,12
    const int brow = t >> 4;        // 0..15
    const int bcol = (t & 15) << 2; // 0..60

    int ar = m0 + arow; if (ar >= M) ar = M - 1;   // clamp; stores are guarded
    const float* Ap = A + (size_t)ar * 128 + acol;
    const float* Bp = B + (size_t)brow * NCOLS + n0 + bcol;

    float4 acc0 = {0,0,0,0}, acc1 = {0,0,0,0}, acc2 = {0,0,0,0}, acc3 = {0,0,0,0};

    for (int k0 = 0; k0 < 128; k0 += 16) {
        float4 av = *reinterpret_cast<const float4*>(Ap + k0);
        As[acol + 0][arow] = av.x;
        As[acol + 1][arow] = av.y;
        As[acol + 2][arow] = av.z;
        As[acol + 3][arow] = av.w;
        *reinterpret_cast<float4*>(&Bs[brow][bcol]) =
            *reinterpret_cast<const float4*>(Bp + (size_t)k0 * NCOLS);
        __syncthreads();
#pragma unroll
        for (int kk = 0; kk < 16; ++kk) {
            float4 a = *reinterpret_cast<const float4*>(&As[kk][ty << 2]);
            float4 b = *reinterpret_cast<const float4*>(&Bs[kk][tx << 2]);
            acc0.x += a.x * b.x; acc0.y += a.x * b.y; acc0.z += a.x * b.z; acc0.w += a.x * b.w;
            acc1.x += a.y * b.x; acc1.y += a.y * b.y; acc1.z += a.y * b.z; acc1.w += a.y * b.w;
            acc2.x += a.z * b.x; acc2.y += a.z * b.y; acc2.z += a.z * b.z; acc2.w += a.z * b.w;
            acc3.x += a.w * b.x; acc3.y += a.w * b.y; acc3.z += a.w * b.z; acc3.w += a.w * b.w;
        }
        __syncthreads();
    }

    const int ocol = n0 + (tx << 2);
    float4 bb = {0,0,0,0};
    if (BIAS) bb = *reinterpret_cast<const float4*>(bias + ocol);

    float4 accs[4] = {acc0, acc1, acc2, acc3};
#pragma unroll
    for (int i = 0; i < 4; ++i) {
        int r = m0 + (ty << 2) + i;
        if (r < M) {
            float4 o = accs[i];
            if (BIAS) { o.x += bb.x; o.y += bb.y; o.z += bb.z; o.w += bb.w; }
            if (RESID) {
                float4 rr = *reinterpret_cast<const float4*>(resid + (size_t)r * NCOLS + ocol);
                o.x += rr.x; o.y += rr.y; o.z += rr.z; o.w += rr.w;
            }
            if (RELU) {
                o.x = fmaxf(o.x, 0.f); o.y = fmaxf(o.y, 0.f);
                o.z = fmaxf(o.z, 0.f); o.w = fmaxf(o.w, 0.f);
            }
            *reinterpret_cast<float4*>(C + (size_t)r * NCOLS + ocol) = o;
        }
    }
}

// ---------------- edge pass 1: score -> exp -> ex[E,8], denom red ----------------
// one warp per edge; lane layout: head = lane/4, sub = lane%4 (4 floats each)
__global__ __launch_bounds__(256)
void edge_pass1(const int* __restrict__ ei, const float* __restrict__ ea,
                const float* __restrict__ Wedge, int E, int n)
{
    int e    = (blockIdx.x * blockDim.x + threadIdx.x) >> 5;
    int lane = threadIdx.x & 31;
    if (e >= E) return;

    int src = clampi(ei[e], n);
    int dst = clampi(ei[E + e], n);
    int hg  = lane >> 2;
    int sub = lane & 3;

    const float* qrow = g_qkv + (size_t)dst * 384;        // q at +0
    const float* krow = g_qkv + (size_t)src * 384 + 128;  // k at +128
    float4 q4 = *reinterpret_cast<const float4*>(qrow + hg * 16 + sub * 4);
    float4 k4 = *reinterpret_cast<const float4*>(krow + hg * 16 + sub * 4);
    float p = q4.x * k4.x + q4.y * k4.y + q4.z * k4.z + q4.w * k4.w;
    p += __shfl_xor_sync(0xffffffffu, p, 1);
    p += __shfl_xor_sync(0xffffffffu, p, 2);   // all 4 lanes of the group hold head dot

    float2 eav = *reinterpret_cast<const float2*>(ea + (size_t)e * 2);
    float biasv = eav.x * Wedge[hg] + eav.y * Wedge[8 + hg];
    float s = p * 0.25f + biasv;               // scale = D^-0.5 = 0.25
    float exv = __expf(s);                     // softmax shift-invariant; scores bounded

    // pack heads 0..3 on lane 0, heads 4..7 on lane 16
    int base = lane & 16;
    float v0 = __shfl_sync(0xffffffffu, exv, base + 0);
    float v1 = __shfl_sync(0xffffffffu, exv, base + 4);
    float v2 = __shfl_sync(0xffffffffu, exv, base + 8);
    float v3 = __shfl_sync(0xffffffffu, exv, base + 12);

    if ((lane & 15) == 0) {
        int off = lane >> 2;   // 0 or 4
        float4 f = {v0, v1, v2, v3};
        *reinterpret_cast<float4*>(g_ex + (size_t)e * 8 + off) = f;
        red_add_v4(g_denom + (size_t)dst * 8 + off, v0, v1, v2, v3);
    }
}

// ---------------- edge pass 2: w = ex/denom ; agg[dst] += v[src]*w ----------------
__global__ __launch_bounds__(256)
void edge_pass2(const int* __restrict__ ei, int E, int n)
{
    int e    = (blockIdx.x * blockDim.x + threadIdx.x) >> 5;
    int lane = threadIdx.x & 31;
    if (e >= E) return;

    int src = clampi(ei[e], n);
    int dst = clampi(ei[E + e], n);
    int hg  = lane >> 2;

    float exv = g_ex[(size_t)e * 8 + hg];
    float den = g_denom[(size_t)dst * 8 + hg];
    float w = exv / (den + 1e-16f);

    float4 v4 = *reinterpret_cast<const float4*>(g_qkv + (size_t)src * 384 + 256 + lane * 4);
    red_add_v4(g_agg + (size_t)dst * 128 + lane * 4,
               v4.x * w, v4.y * w, v4.z * w, v4.w * w);
}

// ---------------- layernorm: one warp per node ----------------
__global__ __launch_bounds__(256)
void ln_kernel(const float* __restrict__ lw, const float* __restrict__ lb, int n)
{
    int node = (blockIdx.x * blockDim.x + threadIdx.x) >> 5;
    int lane = threadIdx.x & 31;
    if (node >= n) return;

    float4 v = *reinterpret_cast<const float4*>(g_h + (size_t)node * 128 + lane * 4);
    float s = v.x + v.y + v.z + v.w;
    float q = v.x * v.x + v.y * v.y + v.z * v.z + v.w * v.w;
#pragma unroll
    for (int o = 16; o; o >>= 1) {
        s += __shfl_xor_sync(0xffffffffu, s, o);
        q += __shfl_xor_sync(0xffffffffu, q, o);
    }
    float mu  = s * (1.f / 128.f);
    float var = q * (1.f / 128.f) - mu * mu;
    float rs  = rsqrtf(var + 1e-5f);
    float4 w4 = *reinterpret_cast<const float4*>(lw + lane * 4);
    float4 b4 = *reinterpret_cast<const float4*>(lb + lane * 4);
    float4 o;
    o.x = (v.x - mu) * rs * w4.x + b4.x;
    o.y = (v.y - mu) * rs * w4.y + b4.y;
    o.z = (v.z - mu) * rs * w4.z + b4.z;
    o.w = (v.w - mu) * rs * w4.w + b4.w;
    *reinterpret_cast<float4*>(g_hn + (size_t)node * 128 + lane * 4) = o;
}

// ---------------- final: out[N,3] = t2[N,64] @ Wc2[64,3] + bc2 ----------------
__global__ __launch_bounds__(256)
void final_kernel(const float* __restrict__ Wc2, const float* __restrict__ bc2,
                  float* __restrict__ out, int n)
{
    int node = (blockIdx.x * blockDim.x + threadIdx.x) >> 5;
    int lane = threadIdx.x & 31;
    if (node >= n) return;

    float2 tv = *reinterpret_cast<const float2*>(g_t2 + (size_t)node * 64 + lane * 2);
    int k0 = lane * 2;
    float s0 = tv.x * Wc2[k0 * 3 + 0] + tv.y * Wc2[k0 * 3 + 3];
    float s1 = tv.x * Wc2[k0 * 3 + 1] + tv.y * Wc2[k0 * 3 + 4];
    float s2 = tv.x * Wc2[k0 * 3 + 2] + tv.y * Wc2[k0 * 3 + 5];
#pragma unroll
    for (int o = 16; o; o >>= 1) {
        s0 += __shfl_xor_sync(0xffffffffu, s0, o);
        s1 += __shfl_xor_sync(0xffffffffu, s1, o);
        s2 += __shfl_xor_sync(0xffffffffu, s2, o);
    }
    if (lane == 0) {
        out[(size_t)node * 3 + 0] = s0 + bc2[0];
        out[(size_t)node * 3 + 1] = s1 + bc2[1];
        out[(size_t)node * 3 + 2] = s2 + bc2[2];
    }
}

// ---------------- launch ----------------
extern "C" void kernel_launch(void* const* d_in, const int* in_sizes, int n_in,
                              void* d_out, int out_size)
{
    const float* x     = (const float*)d_in[0];
    const int*   ei    = (const int*)d_in[1];     // int32 (JAX x64 disabled downcasts int64)
    const float* ea    = (const float*)d_in[2];
    const float* Wqkv  = (const float*)d_in[3];
    const float* Wedge = (const float*)d_in[4];
    const float* Wout  = (const float*)d_in[5];
    const float* bout  = (const float*)d_in[6];
    const float* lnw   = (const float*)d_in[7];
    const float* lnb   = (const float*)d_in[8];
    const float* Wc1   = (const float*)d_in[9];
    const float* bc1   = (const float*)d_in[10];
    const float* Wc2   = (const float*)d_in[11];
    const float* bc2   = (const float*)d_in[12];
    float* out = (float*)d_out;

    const int n = in_sizes[0] / 128;
    const int E = in_sizes[1] / 2;

    float *qkv, *agg, *h, *hn, *t2;
    cudaGetSymbolAddress((void**)&qkv, g_qkv);
    cudaGetSymbolAddress((void**)&agg, g_agg);
    cudaGetSymbolAddress((void**)&h,   g_h);
    cudaGetSymbolAddress((void**)&hn,  g_hn);
    cudaGetSymbolAddress((void**)&t2,  g_t2);

    // 1. zero denom/agg (required each graph replay)
    zero_kernel<<<(n * 32 + 255) / 256, 256>>>(n);

    // 2. qkv = x @ Wqkv   [N,384]
    sgemm_k128<384, false, false, false>
        <<<dim3((n + 63) / 64, 6), 256>>>(x, Wqkv, nullptr, nullptr, qkv, n);

    // 3. per-edge scores -> exp -> denom
    edge_pass1<<<(E + 7) / 8, 256>>>(ei, ea, Wedge, E, n);

    // 4. per-edge weighted V scatter
    edge_pass2<<<(E + 7) / 8, 256>>>(ei, E, n);

    // 5. h = agg @ Wout + bout + x   [N,128]
    sgemm_k128<128, true, true, false>
        <<<dim3((n + 63) / 64, 2), 256>>>(agg, Wout, bout, x, h, n);

    // 6. layernorm
    ln_kernel<<<(n + 7) / 8, 256>>>(lnw, lnb, n);

    // 7. t2 = relu(hn @ Wc1 + bc1)  [N,64]
    sgemm_k128<64, true, false, true>
        <<<dim3((n + 63) / 64, 1), 256>>>(hn, Wc1, bc1, nullptr, t2, n);

    // 8. out = t2 @ Wc2 + bc2  [N,3]
    final_kernel<<<(n + 7) / 8, 256>>>(Wc2, bc2, out, n);
}

// round 3
// speedup vs baseline: 1.0135x; 1.0135x over previous
#include <cuda_runtime.h>
#include <stdint.h>

#define NMAX 100000
#define EMAX 1600000

// ---------------- scratch (static device globals) ----------------
// qkv planes: q = [0, N*128), k = [N*128, 2N*128), v = [2N*128, 3N*128)
__device__ __align__(16) float g_qkv[(size_t)3 * NMAX * 128];
__device__ __align__(16) float g_ex[(size_t)EMAX * 8];
__device__ __align__(16) float g_denom[NMAX * 8];
__device__ __align__(16) float g_agg[NMAX * 128];
__device__ __align__(16) float g_h[NMAX * 128];
__device__ __align__(16) float g_hn[NMAX * 128];
__device__ __align__(16) float g_t2[NMAX * 64];

__device__ __forceinline__ void red_add_v4(float* p, float a, float b, float c, float d) {
    asm volatile("red.global.add.v4.f32 [%0], {%1,%2,%3,%4};"
                 :: "l"(p), "f"(a), "f"(b), "f"(c), "f"(d) : "memory");
}
__device__ __forceinline__ int clampi(int v, int hi) {
    return v < 0 ? 0 : (v >= hi ? hi - 1 : v);
}
// packed fp32x2 FMA (Blackwell): c.lo += a.lo*b.lo ; c.hi += a.hi*b.hi
__device__ __forceinline__ void ffma2(unsigned long long& c, unsigned long long a, unsigned long long b) {
    asm("fma.rn.f32x2 %0, %1, %2, %0;" : "+l"(c) : "l"(a), "l"(b));
}
__device__ __forceinline__ unsigned long long pack2(float x) {
    unsigned long long r;
    asm("mov.b64 %0, {%1, %1};" : "=l"(r) : "f"(x));
    return r;
}
__device__ __forceinline__ float2 unpack2(unsigned long long v) {
    float2 f;
    asm("mov.b64 {%0, %1}, %2;" : "=f"(f.x), "=f"(f.y) : "l"(v));
    return f;
}

// ---------------- zero-init denom + agg ----------------
__global__ void zero_kernel(int n) {
    int i = blockIdx.x * blockDim.x + threadIdx.x;
    float4 z = {0.f, 0.f, 0.f, 0.f};
    int nd = n * 2;
    int na = n * 32;
    if (i < nd) reinterpret_cast<float4*>(g_denom)[i] = z;
    if (i < na) reinterpret_cast<float4*>(g_agg)[i] = z;
}

// ---------------- 128x128x128 sgemm with fp32x2 FMAs ----------------
// C[M, out] = A[M,128] @ B[128,NCOLS] (+bias)(+resid)(relu)
// SPLIT: B has NCOLS=384; output plane p = n0/128 written to C + p*M*128 (stride 128)
template<bool BIAS, bool RESID, bool RELU, bool SPLIT>
__global__ __launch_bounds__(256, 2)
void sgemm_f32x2(const float* __restrict__ A, const float* __restrict__ B,
                 const float* __restrict__ bias, const float* __restrict__ resid,
                 float* __restrict__ C, int M, int NCOLS)
{
    __shared__ __align__(16) float As[8][128];
    __shared__ __align__(16) float Bs[8][128];

    const int t  = threadIdx.x;
    const int m0 = blockIdx.x * 128;
    const int n0 = blockIdx.y * 128;

    const int am = t >> 1;            // 0..127 (A tile row)
    const int aq = (t & 1) * 4;       // k sub-offset 0/4
    const int brow = t >> 5;          // 0..7
    const int bcol = (t & 31) * 4;    // 0..124

    const int tx = t & 15;            // col group (8 cols)
    const int ty = t >> 4;            // row group (8 rows)

    int ar = m0 + am; if (ar >= M) ar = M - 1;
    const float* Ap = A + (size_t)ar * 128 + aq;
    const float* Bp = B + (size_t)brow * NCOLS + n0 + bcol;

    unsigned long long acc[8][4];
#pragma unroll
    for (int i = 0; i < 8; ++i)
#pragma unroll
        for (int j = 0; j < 4; ++j) acc[i][j] = 0ull;

    for (int k0 = 0; k0 < 128; k0 += 8) {
        float4 av = *reinterpret_cast<const float4*>(Ap + k0);
        As[aq + 0][am] = av.x;
        As[aq + 1][am] = av.y;
        As[aq + 2][am] = av.z;
        As[aq + 3][am] = av.w;
        *reinterpret_cast<float4*>(&Bs[brow][bcol]) =
            *reinterpret_cast<const float4*>(Bp + (size_t)k0 * NCOLS);
        __syncthreads();
#pragma unroll
        for (int kk = 0; kk < 8; ++kk) {
            const float* as = &As[kk][ty * 8];
            float4 a0 = *reinterpret_cast<const float4*>(as);
            float4 a1 = *reinterpret_cast<const float4*>(as + 4);
            const unsigned long long* bp =
                reinterpret_cast<const unsigned long long*>(&Bs[kk][tx * 8]);
            unsigned long long b0 = bp[0], b1 = bp[1], b2 = bp[2], b3 = bp[3];
            float aa[8] = {a0.x, a0.y, a0.z, a0.w, a1.x, a1.y, a1.z, a1.w};
#pragma unroll
            for (int i = 0; i < 8; ++i) {
                unsigned long long ap = pack2(aa[i]);
                ffma2(acc[i][0], ap, b0);
                ffma2(acc[i][1], ap, b1);
                ffma2(acc[i][2], ap, b2);
                ffma2(acc[i][3], ap, b3);
            }
        }
        __syncthreads();
    }

    // epilogue
    const int colg = tx * 8;                 // col within 128-wide tile
    float bb[8];
    if (BIAS) {
#pragma unroll
        for (int j = 0; j < 8; ++j) bb[j] = bias[n0 + colg + j];
    }
    float* Cbase;
    int cstride;
    if (SPLIT) { Cbase = C + (size_t)(n0 >> 7) * (size_t)M * 128; cstride = 128; }
    else       { Cbase = C + n0; cstride = NCOLS; }

#pragma unroll
    for (int i = 0; i < 8; ++i) {
        int r = m0 + ty * 8 + i;
        if (r < M) {
            float c[8];
#pragma unroll
            for (int j = 0; j < 4; ++j) {
                float2 f = unpack2(acc[i][j]);
                c[2 * j] = f.x; c[2 * j + 1] = f.y;
            }
            if (BIAS) {
#pragma unroll
                for (int j = 0; j < 8; ++j) c[j] += bb[j];
            }
            if (RESID) {
                const float* rp = resid + (size_t)r * 128 + n0 + colg;
                float4 r0 = *reinterpret_cast<const float4*>(rp);
                float4 r1 = *reinterpret_cast<const float4*>(rp + 4);
                c[0] += r0.x; c[1] += r0.y; c[2] += r0.z; c[3] += r0.w;
                c[4] += r1.x; c[5] += r1.y; c[6] += r1.z; c[7] += r1.w;
            }
            if (RELU) {
#pragma unroll
                for (int j = 0; j < 8; ++j) c[j] = fmaxf(c[j], 0.f);
            }
            float* cp = Cbase + (size_t)r * cstride + colg;
            float4 o0 = {c[0], c[1], c[2], c[3]};
            float4 o1 = {c[4], c[5], c[6], c[7]};
            *reinterpret_cast<float4*>(cp) = o0;
            *reinterpret_cast<float4*>(cp + 4) = o1;
        }
    }
}

// ---------------- small sgemm (64-wide tiles) for Wc1 ----------------
template<int NCOLS, bool BIAS, bool RELU>
__global__ __launch_bounds__(256)
void sgemm_k128s(const float* __restrict__ A, const float* __restrict__ B,
                 const float* __restrict__ bias, float* __restrict__ C, int M)
{
    __shared__ __align__(16) float As[16][64];
    __shared__ __align__(16) float Bs[16][64];

    const int t  = threadIdx.x;
    const int m0 = blockIdx.x * 64;
    const int n0 = blockIdx.y * 64;
    const int tx = t & 15;
    const int ty = t >> 4;
    const int arow = t >> 2;
    const int acol = (t & 3) << 2;
    const int brow = t >> 4;
    const int bcol = (t & 15) << 2;

    int ar = m0 + arow; if (ar >= M) ar = M - 1;
    const float* Ap = A + (size_t)ar * 128 + acol;
    const float* Bp = B + (size_t)brow * NCOLS + n0 + bcol;

    float4 acc0 = {0,0,0,0}, acc1 = {0,0,0,0}, acc2 = {0,0,0,0}, acc3 = {0,0,0,0};

    for (int k0 = 0; k0 < 128; k0 += 16) {
        float4 av = *reinterpret_cast<const float4*>(Ap + k0);
        As[acol + 0][arow] = av.x;
        As[acol + 1][arow] = av.y;
        As[acol + 2][arow] = av.z;
        As[acol + 3][arow] = av.w;
        *reinterpret_cast<float4*>(&Bs[brow][bcol]) =
            *reinterpret_cast<const float4*>(Bp + (size_t)k0 * NCOLS);
        __syncthreads();
#pragma unroll
        for (int kk = 0; kk < 16; ++kk) {
            float4 a = *reinterpret_cast<const float4*>(&As[kk][ty << 2]);
            float4 b = *reinterpret_cast<const float4*>(&Bs[kk][tx << 2]);
            acc0.x += a.x * b.x; acc0.y += a.x * b.y; acc0.z += a.x * b.z; acc0.w += a.x * b.w;
            acc1.x += a.y * b.x; acc1.y += a.y * b.y; acc1.z += a.y * b.z; acc1.w += a.y * b.w;
            acc2.x += a.z * b.x; acc2.y += a.z * b.y; acc2.z += a.z * b.z; acc2.w += a.z * b.w;
            acc3.x += a.w * b.x; acc3.y += a.w * b.y; acc3.z += a.w * b.z; acc3.w += a.w * b.w;
        }
        __syncthreads();
    }

    const int ocol = n0 + (tx << 2);
    float4 bb = {0,0,0,0};
    if (BIAS) bb = *reinterpret_cast<const float4*>(bias + ocol);

    float4 accs[4] = {acc0, acc1, acc2, acc3};
#pragma unroll
    for (int i = 0; i < 4; ++i) {
        int r = m0 + (ty << 2) + i;
        if (r < M) {
            float4 o = accs[i];
            if (BIAS) { o.x += bb.x; o.y += bb.y; o.z += bb.z; o.w += bb.w; }
            if (RELU) {
                o.x = fmaxf(o.x, 0.f); o.y = fmaxf(o.y, 0.f);
                o.z = fmaxf(o.z, 0.f); o.w = fmaxf(o.w, 0.f);
            }
            *reinterpret_cast<float4*>(C + (size_t)r * NCOLS + ocol) = o;
        }
    }
}

// ---------------- edge pass 1 ----------------
__global__ __launch_bounds__(256)
void edge_pass1(const int* __restrict__ ei, const float* __restrict__ ea,
                const float* __restrict__ Wedge, int E, int n)
{
    int e    = (blockIdx.x * blockDim.x + threadIdx.x) >> 5;
    int lane = threadIdx.x & 31;
    if (e >= E) return;

    int src = clampi(ei[e], n);
    int dst = clampi(ei[E + e], n);
    int hg  = lane >> 2;

    const float* qrow = g_qkv + (size_t)dst * 128;                    // q plane
    const float* krow = g_qkv + (size_t)n * 128 + (size_t)src * 128;  // k plane
    float4 q4 = *reinterpret_cast<const float4*>(qrow + lane * 4);
    float4 k4 = *reinterpret_cast<const float4*>(krow + lane * 4);
    float p = q4.x * k4.x + q4.y * k4.y + q4.z * k4.z + q4.w * k4.w;
    p += __shfl_xor_sync(0xffffffffu, p, 1);
    p += __shfl_xor_sync(0xffffffffu, p, 2);

    float2 eav = *reinterpret_cast<const float2*>(ea + (size_t)e * 2);
    float biasv = eav.x * Wedge[hg] + eav.y * Wedge[8 + hg];
    float s = p * 0.25f + biasv;
    float exv = __expf(s);

    int base = lane & 16;
    float v0 = __shfl_sync(0xffffffffu, exv, base + 0);
    float v1 = __shfl_sync(0xffffffffu, exv, base + 4);
    float v2 = __shfl_sync(0xffffffffu, exv, base + 8);
    float v3 = __shfl_sync(0xffffffffu, exv, base + 12);

    if ((lane & 15) == 0) {
        int off = lane >> 2;
        float4 f = {v0, v1, v2, v3};
        __stcs(reinterpret_cast<float4*>(g_ex + (size_t)e * 8 + off), f);   // streaming
        red_add_v4(g_denom + (size_t)dst * 8 + off, v0, v1, v2, v3);
    }
}

// ---------------- edge pass 2 ----------------
__global__ __launch_bounds__(256)
void edge_pass2(const int* __restrict__ ei, int E, int n)
{
    int e    = (blockIdx.x * blockDim.x + threadIdx.x) >> 5;
    int lane = threadIdx.x & 31;
    if (e >= E) return;

    int src = clampi(ei[e], n);
    int dst = clampi(ei[E + e], n);
    int hg  = lane >> 2;

    float exv = __ldcs(g_ex + (size_t)e * 8 + hg);     // streaming read
    float den = g_denom[(size_t)dst * 8 + hg];
    float w = exv / (den + 1e-16f);

    const float* vrow = g_qkv + (size_t)2 * n * 128 + (size_t)src * 128;  // v plane
    float4 v4 = *reinterpret_cast<const float4*>(vrow + lane * 4);
    red_add_v4(g_agg + (size_t)dst * 128 + lane * 4,
               v4.x * w, v4.y * w, v4.z * w, v4.w * w);
}

// ---------------- layernorm ----------------
__global__ __launch_bounds__(256)
void ln_kernel(const float* __restrict__ lw, const float* __restrict__ lb, int n)
{
    int node = (blockIdx.x * blockDim.x + threadIdx.x) >> 5;
    int lane = threadIdx.x & 31;
    if (node >= n) return;

    float4 v = *reinterpret_cast<const float4*>(g_h + (size_t)node * 128 + lane * 4);
    float s = v.x + v.y + v.z + v.w;
    float q = v.x * v.x + v.y * v.y + v.z * v.z + v.w * v.w;
#pragma unroll
    for (int o = 16; o; o >>= 1) {
        s += __shfl_xor_sync(0xffffffffu, s, o);
        q += __shfl_xor_sync(0xffffffffu, q, o);
    }
    float mu  = s * (1.f / 128.f);
    float var = q * (1.f / 128.f) - mu * mu;
    float rs  = rsqrtf(var + 1e-5f);
    float4 w4 = *reinterpret_cast<const float4*>(lw + lane * 4);
    float4 b4 = *reinterpret_cast<const float4*>(lb + lane * 4);
    float4 o;
    o.x = (v.x - mu) * rs * w4.x + b4.x;
    o.y = (v.y - mu) * rs * w4.y + b4.y;
    o.z = (v.z - mu) * rs * w4.z + b4.z;
    o.w = (v.w - mu) * rs * w4.w + b4.w;
    *reinterpret_cast<float4*>(g_hn + (size_t)node * 128 + lane * 4) = o;
}

// ---------------- final: out[N,3] = t2[N,64] @ Wc2[64,3] + bc2 ----------------
__global__ __launch_bounds__(256)
void final_kernel(const float* __restrict__ Wc2, const float* __restrict__ bc2,
                  float* __restrict__ out, int n)
{
    int node = (blockIdx.x * blockDim.x + threadIdx.x) >> 5;
    int lane = threadIdx.x & 31;
    if (node >= n) return;

    float2 tv = *reinterpret_cast<const float2*>(g_t2 + (size_t)node * 64 + lane * 2);
    int k0 = lane * 2;
    float s0 = tv.x * Wc2[k0 * 3 + 0] + tv.y * Wc2[k0 * 3 + 3];
    float s1 = tv.x * Wc2[k0 * 3 + 1] + tv.y * Wc2[k0 * 3 + 4];
    float s2 = tv.x * Wc2[k0 * 3 + 2] + tv.y * Wc2[k0 * 3 + 5];
#pragma unroll
    for (int o = 16; o; o >>= 1) {
        s0 += __shfl_xor_sync(0xffffffffu, s0, o);
        s1 += __shfl_xor_sync(0xffffffffu, s1, o);
        s2 += __shfl_xor_sync(0xffffffffu, s2, o);
    }
    if (lane == 0) {
        out[(size_t)node * 3 + 0] = s0 + bc2[0];
        out[(size_t)node * 3 + 1] = s1 + bc2[1];
        out[(size_t)node * 3 + 2] = s2 + bc2[2];
    }
}

// ---------------- launch ----------------
extern "C" void kernel_launch(void* const* d_in, const int* in_sizes, int n_in,
                              void* d_out, int out_size)
{
    const float* x     = (const float*)d_in[0];
    const int*   ei    = (const int*)d_in[1];
    const float* ea    = (const float*)d_in[2];
    const float* Wqkv  = (const float*)d_in[3];
    const float* Wedge = (const float*)d_in[4];
    const float* Wout  = (const float*)d_in[5];
    const float* bout  = (const float*)d_in[6];
    const float* lnw   = (const float*)d_in[7];
    const float* lnb   = (const float*)d_in[8];
    const float* Wc1   = (const float*)d_in[9];
    const float* bc1   = (const float*)d_in[10];
    const float* Wc2   = (const float*)d_in[11];
    const float* bc2   = (const float*)d_in[12];
    float* out = (float*)d_out;

    const int n = in_sizes[0] / 128;
    const int E = in_sizes[1] / 2;

    float *qkv, *agg, *h, *hn, *t2;
    cudaGetSymbolAddress((void**)&qkv, g_qkv);
    cudaGetSymbolAddress((void**)&agg, g_agg);
    cudaGetSymbolAddress((void**)&h,   g_h);
    cudaGetSymbolAddress((void**)&hn,  g_hn);
    cudaGetSymbolAddress((void**)&t2,  g_t2);

    // 1. zero denom/agg
    zero_kernel<<<(n * 32 + 255) / 256, 256>>>(n);

    // 2. qkv = x @ Wqkv -> q/k/v planes
    sgemm_f32x2<false, false, false, true>
        <<<dim3((n + 127) / 128, 3), 256>>>(x, Wqkv, nullptr, nullptr, qkv, n, 384);

    // 3. per-edge scores -> exp -> denom
    edge_pass1<<<(E + 7) / 8, 256>>>(ei, ea, Wedge, E, n);

    // 4. per-edge weighted V scatter
    edge_pass2<<<(E + 7) / 8, 256>>>(ei, E, n);

    // 5. h = agg @ Wout + bout + x
    sgemm_f32x2<true, true, false, false>
        <<<dim3((n + 127) / 128, 1), 256>>>(agg, Wout, bout, x, h, n, 128);

    // 6. layernorm
    ln_kernel<<<(n + 7) / 8, 256>>>(lnw, lnb, n);

    // 7. t2 = relu(hn @ Wc1 + bc1)
    sgemm_k128s<64, true, true>
        <<<dim3((n + 63) / 64, 1), 256>>>(hn, Wc1, bc1, t2, n);

    // 8. out = t2 @ Wc2 + bc2
    final_kernel<<<(n + 7) / 8, 256>>>(Wc2, bc2, out, n);
}

// round 4
// speedup vs baseline: 1.2105x; 1.1944x over previous
#include <cuda_runtime.h>
#include <stdint.h>

#define NMAX 100000
#define EMAX 1600000

// ---------------- scratch (static device globals) ----------------
// qkv planes: q = [0, N*128), k = [N*128, 2N*128), v = [2N*128, 3N*128)
__device__ __align__(16) float g_qkv[(size_t)3 * NMAX * 128];
__device__ __align__(16) float g_ex[(size_t)EMAX * 8];
__device__ __align__(16) float g_denom[NMAX * 8];
__device__ __align__(16) float g_agg[NMAX * 128];
__device__ __align__(16) float g_h[NMAX * 128];
__device__ __align__(16) float g_hn[NMAX * 128];
__device__ __align__(16) float g_t2[NMAX * 64];

__device__ __forceinline__ void red_add_v4(float* p, float a, float b, float c, float d) {
    asm volatile("red.global.add.v4.f32 [%0], {%1,%2,%3,%4};"
                 :: "l"(p), "f"(a), "f"(b), "f"(c), "f"(d) : "memory");
}
__device__ __forceinline__ int clampi(int v, int hi) {
    return v < 0 ? 0 : (v >= hi ? hi - 1 : v);
}
// packed fp32x2 FMA (Blackwell)
__device__ __forceinline__ void ffma2(unsigned long long& c, unsigned long long a, unsigned long long b) {
    asm("fma.rn.f32x2 %0, %1, %2, %0;" : "+l"(c) : "l"(a), "l"(b));
}
__device__ __forceinline__ unsigned long long pack2(float x) {
    unsigned long long r;
    asm("mov.b64 %0, {%1, %1};" : "=l"(r) : "f"(x));
    return r;
}
__device__ __forceinline__ float2 unpack2(unsigned long long v) {
    float2 f;
    asm("mov.b64 {%0, %1}, %2;" : "=f"(f.x), "=f"(f.y) : "l"(v));
    return f;
}

// ---------------- zero-init denom + agg ----------------
__global__ void zero_kernel(int n) {
    int i = blockIdx.x * blockDim.x + threadIdx.x;
    float4 z = {0.f, 0.f, 0.f, 0.f};
    int nd = n * 2;
    int na = n * 32;
    if (i < nd) reinterpret_cast<float4*>(g_denom)[i] = z;
    if (i < na) reinterpret_cast<float4*>(g_agg)[i] = z;
}

// ---------------- 128x128x128 sgemm with fp32x2 FMAs ----------------
template<bool BIAS, bool RESID, bool RELU, bool SPLIT>
__global__ __launch_bounds__(256, 2)
void sgemm_f32x2(const float* __restrict__ A, const float* __restrict__ B,
                 const float* __restrict__ bias, const float* __restrict__ resid,
                 float* __restrict__ C, int M, int NCOLS)
{
    __shared__ __align__(16) float As[8][128];
    __shared__ __align__(16) float Bs[8][128];

    const int t  = threadIdx.x;
    const int m0 = blockIdx.x * 128;
    const int n0 = blockIdx.y * 128;

    const int am = t >> 1;
    const int aq = (t & 1) * 4;
    const int brow = t >> 5;
    const int bcol = (t & 31) * 4;

    const int tx = t & 15;
    const int ty = t >> 4;

    int ar = m0 + am; if (ar >= M) ar = M - 1;
    const float* Ap = A + (size_t)ar * 128 + aq;
    const float* Bp = B + (size_t)brow * NCOLS + n0 + bcol;

    unsigned long long acc[8][4];
#pragma unroll
    for (int i = 0; i < 8; ++i)
#pragma unroll
        for (int j = 0; j < 4; ++j) acc[i][j] = 0ull;

    for (int k0 = 0; k0 < 128; k0 += 8) {
        float4 av = *reinterpret_cast<const float4*>(Ap + k0);
        As[aq + 0][am] = av.x;
        As[aq + 1][am] = av.y;
        As[aq + 2][am] = av.z;
        As[aq + 3][am] = av.w;
        *reinterpret_cast<float4*>(&Bs[brow][bcol]) =
            *reinterpret_cast<const float4*>(Bp + (size_t)k0 * NCOLS);
        __syncthreads();
#pragma unroll
        for (int kk = 0; kk < 8; ++kk) {
            const float* as = &As[kk][ty * 8];
            float4 a0 = *reinterpret_cast<const float4*>(as);
            float4 a1 = *reinterpret_cast<const float4*>(as + 4);
            const unsigned long long* bp =
                reinterpret_cast<const unsigned long long*>(&Bs[kk][tx * 8]);
            unsigned long long b0 = bp[0], b1 = bp[1], b2 = bp[2], b3 = bp[3];
            float aa[8] = {a0.x, a0.y, a0.z, a0.w, a1.x, a1.y, a1.z, a1.w};
#pragma unroll
            for (int i = 0; i < 8; ++i) {
                unsigned long long ap = pack2(aa[i]);
                ffma2(acc[i][0], ap, b0);
                ffma2(acc[i][1], ap, b1);
                ffma2(acc[i][2], ap, b2);
                ffma2(acc[i][3], ap, b3);
            }
        }
        __syncthreads();
    }

    const int colg = tx * 8;
    float bb[8];
    if (BIAS) {
#pragma unroll
        for (int j = 0; j < 8; ++j) bb[j] = bias[n0 + colg + j];
    }
    float* Cbase;
    int cstride;
    if (SPLIT) { Cbase = C + (size_t)(n0 >> 7) * (size_t)M * 128; cstride = 128; }
    else       { Cbase = C + n0; cstride = NCOLS; }

#pragma unroll
    for (int i = 0; i < 8; ++i) {
        int r = m0 + ty * 8 + i;
        if (r < M) {
            float c[8];
#pragma unroll
            for (int j = 0; j < 4; ++j) {
                float2 f = unpack2(acc[i][j]);
                c[2 * j] = f.x; c[2 * j + 1] = f.y;
            }
            if (BIAS) {
#pragma unroll
                for (int j = 0; j < 8; ++j) c[j] += bb[j];
            }
            if (RESID) {
                const float* rp = resid + (size_t)r * 128 + n0 + colg;
                float4 r0 = *reinterpret_cast<const float4*>(rp);
                float4 r1 = *reinterpret_cast<const float4*>(rp + 4);
                c[0] += r0.x; c[1] += r0.y; c[2] += r0.z; c[3] += r0.w;
                c[4] += r1.x; c[5] += r1.y; c[6] += r1.z; c[7] += r1.w;
            }
            if (RELU) {
#pragma unroll
                for (int j = 0; j < 8; ++j) c[j] = fmaxf(c[j], 0.f);
            }
            float* cp = Cbase + (size_t)r * cstride + colg;
            float4 o0 = {c[0], c[1], c[2], c[3]};
            float4 o1 = {c[4], c[5], c[6], c[7]};
            *reinterpret_cast<float4*>(cp) = o0;
            *reinterpret_cast<float4*>(cp + 4) = o1;
        }
    }
}

// ---------------- small sgemm (64-wide tiles) for Wc1 ----------------
template<int NCOLS, bool BIAS, bool RELU>
__global__ __launch_bounds__(256)
void sgemm_k128s(const float* __restrict__ A, const float* __restrict__ B,
                 const float* __restrict__ bias, float* __restrict__ C, int M)
{
    __shared__ __align__(16) float As[16][64];
    __shared__ __align__(16) float Bs[16][64];

    const int t  = threadIdx.x;
    const int m0 = blockIdx.x * 64;
    const int n0 = blockIdx.y * 64;
    const int tx = t & 15;
    const int ty = t >> 4;
    const int arow = t >> 2;
    const int acol = (t & 3) << 2;
    const int brow = t >> 4;
    const int bcol = (t & 15) << 2;

    int ar = m0 + arow; if (ar >= M) ar = M - 1;
    const float* Ap = A + (size_t)ar * 128 + acol;
    const float* Bp = B + (size_t)brow * NCOLS + n0 + bcol;

    float4 acc0 = {0,0,0,0}, acc1 = {0,0,0,0}, acc2 = {0,0,0,0}, acc3 = {0,0,0,0};

    for (int k0 = 0; k0 < 128; k0 += 16) {
        float4 av = *reinterpret_cast<const float4*>(Ap + k0);
        As[acol + 0][arow] = av.x;
        As[acol + 1][arow] = av.y;
        As[acol + 2][arow] = av.z;
        As[acol + 3][arow] = av.w;
        *reinterpret_cast<float4*>(&Bs[brow][bcol]) =
            *reinterpret_cast<const float4*>(Bp + (size_t)k0 * NCOLS);
        __syncthreads();
#pragma unroll
        for (int kk = 0; kk < 16; ++kk) {
            float4 a = *reinterpret_cast<const float4*>(&As[kk][ty << 2]);
            float4 b = *reinterpret_cast<const float4*>(&Bs[kk][tx << 2]);
            acc0.x += a.x * b.x; acc0.y += a.x * b.y; acc0.z += a.x * b.z; acc0.w += a.x * b.w;
            acc1.x += a.y * b.x; acc1.y += a.y * b.y; acc1.z += a.y * b.z; acc1.w += a.y * b.w;
            acc2.x += a.z * b.x; acc2.y += a.z * b.y; acc2.z += a.z * b.z; acc2.w += a.z * b.w;
            acc3.x += a.w * b.x; acc3.y += a.w * b.y; acc3.z += a.w * b.z; acc3.w += a.w * b.w;
        }
        __syncthreads();
    }

    const int ocol = n0 + (tx << 2);
    float4 bb = {0,0,0,0};
    if (BIAS) bb = *reinterpret_cast<const float4*>(bias + ocol);

    float4 accs[4] = {acc0, acc1, acc2, acc3};
#pragma unroll
    for (int i = 0; i < 4; ++i) {
        int r = m0 + (ty << 2) + i;
        if (r < M) {
            float4 o = accs[i];
            if (BIAS) { o.x += bb.x; o.y += bb.y; o.z += bb.z; o.w += bb.w; }
            if (RELU) {
                o.x = fmaxf(o.x, 0.f); o.y = fmaxf(o.y, 0.f);
                o.z = fmaxf(o.z, 0.f); o.w = fmaxf(o.w, 0.f);
            }
            *reinterpret_cast<float4*>(C + (size_t)r * NCOLS + ocol) = o;
        }
    }
}

// ---------------- edge pass 1: 2 edges per warp, front-batched gathers ----------------
__global__ __launch_bounds__(256)
void edge_pass1(const int* __restrict__ ei, const float* __restrict__ ea,
                const float* __restrict__ Wedge, int E, int n)
{
    const int EPW = 2;
    int warp = (blockIdx.x * blockDim.x + threadIdx.x) >> 5;
    int lane = threadIdx.x & 31;
    long long e0 = (long long)warp * EPW;
    if (e0 >= E) return;
    int hg = lane >> 2;

    int srcs[EPW], dsts[EPW];
    float2 eav[EPW];
#pragma unroll
    for (int j = 0; j < EPW; ++j) {
        long long e = e0 + j < E ? e0 + j : E - 1;
        srcs[j] = clampi(__ldg(ei + e), n);
        dsts[j] = clampi(__ldg(ei + E + e), n);
        eav[j]  = *reinterpret_cast<const float2*>(ea + e * 2);
    }

    // batched gathers (MLP = 2*EPW)
    float4 q4[EPW], k4[EPW];
#pragma unroll
    for (int j = 0; j < EPW; ++j) {
        q4[j] = *reinterpret_cast<const float4*>(g_qkv + (size_t)dsts[j] * 128 + lane * 4);
        k4[j] = *reinterpret_cast<const float4*>(g_qkv + (size_t)n * 128 + (size_t)srcs[j] * 128 + lane * 4);
    }

    float w0 = Wedge[hg], w1 = Wedge[8 + hg];

#pragma unroll
    for (int j = 0; j < EPW; ++j) {
        float p = q4[j].x * k4[j].x + q4[j].y * k4[j].y + q4[j].z * k4[j].z + q4[j].w * k4[j].w;
        p += __shfl_xor_sync(0xffffffffu, p, 1);
        p += __shfl_xor_sync(0xffffffffu, p, 2);

        float s = p * 0.25f + eav[j].x * w0 + eav[j].y * w1;
        float exv = __expf(s);

        int base = lane & 16;
        float v0 = __shfl_sync(0xffffffffu, exv, base + 0);
        float v1 = __shfl_sync(0xffffffffu, exv, base + 4);
        float v2 = __shfl_sync(0xffffffffu, exv, base + 8);
        float v3 = __shfl_sync(0xffffffffu, exv, base + 12);

        if ((lane & 15) == 0 && e0 + j < E) {
            int off = lane >> 2;
            float4 f = {v0, v1, v2, v3};
            __stcs(reinterpret_cast<float4*>(g_ex + (size_t)(e0 + j) * 8 + off), f);
            red_add_v4(g_denom + (size_t)dsts[j] * 8 + off, v0, v1, v2, v3);
        }
    }
}

// ---------------- edge pass 2: 4 edges per warp, batched gathers ----------------
__global__ __launch_bounds__(256)
void edge_pass2(const int* __restrict__ ei, int E, int n)
{
    const int EPW = 4;
    int warp = (blockIdx.x * blockDim.x + threadIdx.x) >> 5;
    int lane = threadIdx.x & 31;
    long long e0 = (long long)warp * EPW;
    if (e0 >= E) return;
    int hg = lane >> 2;

    const float* vplane = g_qkv + (size_t)2 * n * 128;

    int srcs[EPW], dsts[EPW];
#pragma unroll
    for (int j = 0; j < EPW; ++j) {
        long long e = e0 + j < E ? e0 + j : E - 1;
        srcs[j] = clampi(__ldg(ei + e), n);
        dsts[j] = clampi(__ldg(ei + E + e), n);
    }

    // batch all loads first: ex, denom, v-rows  (MLP = 3*EPW)
    float exv[EPW], den[EPW];
    float4 v4[EPW];
#pragma unroll
    for (int j = 0; j < EPW; ++j) {
        long long e = e0 + j < E ? e0 + j : E - 1;
        exv[j] = __ldcs(g_ex + (size_t)e * 8 + hg);
        den[j] = __ldg(g_denom + (size_t)dsts[j] * 8 + hg);
        v4[j]  = *reinterpret_cast<const float4*>(vplane + (size_t)srcs[j] * 128 + lane * 4);
    }

#pragma unroll
    for (int j = 0; j < EPW; ++j) {
        if (e0 + j < E) {
            float w = __fdividef(exv[j], den[j] + 1e-16f);
            red_add_v4(g_agg + (size_t)dsts[j] * 128 + lane * 4,
                       v4[j].x * w, v4[j].y * w, v4[j].z * w, v4[j].w * w);
        }
    }
}

// ---------------- layernorm ----------------
__global__ __launch_bounds__(256)
void ln_kernel(const float* __restrict__ lw, const float* __restrict__ lb, int n)
{
    int node = (blockIdx.x * blockDim.x + threadIdx.x) >> 5;
    int lane = threadIdx.x & 31;
    if (node >= n) return;

    float4 v = *reinterpret_cast<const float4*>(g_h + (size_t)node * 128 + lane * 4);
    float s = v.x + v.y + v.z + v.w;
    float q = v.x * v.x + v.y * v.y + v.z * v.z + v.w * v.w;
#pragma unroll
    for (int o = 16; o; o >>= 1) {
        s += __shfl_xor_sync(0xffffffffu, s, o);
        q += __shfl_xor_sync(0xffffffffu, q, o);
    }
    float mu  = s * (1.f / 128.f);
    float var = q * (1.f / 128.f) - mu * mu;
    float rs  = rsqrtf(var + 1e-5f);
    float4 w4 = *reinterpret_cast<const float4*>(lw + lane * 4);
    float4 b4 = *reinterpret_cast<const float4*>(lb + lane * 4);
    float4 o;
    o.x = (v.x - mu) * rs * w4.x + b4.x;
    o.y = (v.y - mu) * rs * w4.y + b4.y;
    o.z = (v.z - mu) * rs * w4.z + b4.z;
    o.w = (v.w - mu) * rs * w4.w + b4.w;
    *reinterpret_cast<float4*>(g_hn + (size_t)node * 128 + lane * 4) = o;
}

// ---------------- final: out[N,3] = t2[N,64] @ Wc2[64,3] + bc2 ----------------
__global__ __launch_bounds__(256)
void final_kernel(const float* __restrict__ Wc2, const float* __restrict__ bc2,
                  float* __restrict__ out, int n)
{
    int node = (blockIdx.x * blockDim.x + threadIdx.x) >> 5;
    int lane = threadIdx.x & 31;
    if (node >= n) return;

    float2 tv = *reinterpret_cast<const float2*>(g_t2 + (size_t)node * 64 + lane * 2);
    int k0 = lane * 2;
    float s0 = tv.x * Wc2[k0 * 3 + 0] + tv.y * Wc2[k0 * 3 + 3];
    float s1 = tv.x * Wc2[k0 * 3 + 1] + tv.y * Wc2[k0 * 3 + 4];
    float s2 = tv.x * Wc2[k0 * 3 + 2] + tv.y * Wc2[k0 * 3 + 5];
#pragma unroll
    for (int o = 16; o; o >>= 1) {
        s0 += __shfl_xor_sync(0xffffffffu, s0, o);
        s1 += __shfl_xor_sync(0xffffffffu, s1, o);
        s2 += __shfl_xor_sync(0xffffffffu, s2, o);
    }
    if (lane == 0) {
        out[(size_t)node * 3 + 0] = s0 + bc2[0];
        out[(size_t)node * 3 + 1] = s1 + bc2[1];
        out[(size_t)node * 3 + 2] = s2 + bc2[2];
    }
}

// ---------------- launch ----------------
extern "C" void kernel_launch(void* const* d_in, const int* in_sizes, int n_in,
                              void* d_out, int out_size)
{
    const float* x     = (const float*)d_in[0];
    const int*   ei    = (const int*)d_in[1];
    const float* ea    = (const float*)d_in[2];
    const float* Wqkv  = (const float*)d_in[3];
    const float* Wedge = (const float*)d_in[4];
    const float* Wout  = (const float*)d_in[5];
    const float* bout  = (const float*)d_in[6];
    const float* lnw   = (const float*)d_in[7];
    const float* lnb   = (const float*)d_in[8];
    const float* Wc1   = (const float*)d_in[9];
    const float* bc1   = (const float*)d_in[10];
    const float* Wc2   = (const float*)d_in[11];
    const float* bc2   = (const float*)d_in[12];
    float* out = (float*)d_out;

    const int n = in_sizes[0] / 128;
    const int E = in_sizes[1] / 2;

    float *qkv, *agg, *h, *hn, *t2;
    cudaGetSymbolAddress((void**)&qkv, g_qkv);
    cudaGetSymbolAddress((void**)&agg, g_agg);
    cudaGetSymbolAddress((void**)&h,   g_h);
    cudaGetSymbolAddress((void**)&hn,  g_hn);
    cudaGetSymbolAddress((void**)&t2,  g_t2);

    // 1. zero denom/agg
    zero_kernel<<<(n * 32 + 255) / 256, 256>>>(n);

    // 2. qkv = x @ Wqkv -> q/k/v planes
    sgemm_f32x2<false, false, false, true>
        <<<dim3((n + 127) / 128, 3), 256>>>(x, Wqkv, nullptr, nullptr, qkv, n, 384);

    // 3. per-edge scores -> exp -> denom (2 edges/warp)
    {
        int warps = (E + 1) / 2;
        edge_pass1<<<(warps * 32 + 255) / 256, 256>>>(ei, ea, Wedge, E, n);
    }

    // 4. per-edge weighted V scatter (4 edges/warp)
    {
        int warps = (E + 3) / 4;
        edge_pass2<<<(warps * 32 + 255) / 256, 256>>>(ei, E, n);
    }

    // 5. h = agg @ Wout + bout + x
    sgemm_f32x2<true, true, false, false>
        <<<dim3((n + 127) / 128, 1), 256>>>(agg, Wout, bout, x, h, n, 128);

    // 6. layernorm
    ln_kernel<<<(n + 7) / 8, 256>>>(lnw, lnb, n);

    // 7. t2 = relu(hn @ Wc1 + bc1)
    sgemm_k128s<64, true, true>
        <<<dim3((n + 63) / 64, 1), 256>>>(hn, Wc1, bc1, t2, n);

    // 8. out = t2 @ Wc2 + bc2
    final_kernel<<<(n + 7) / 8, 256>>>(Wc2, bc2, out, n);
}

// round 5
// speedup vs baseline: 1.3443x; 1.1105x over previous
#include <cuda_runtime.h>
#include <cuda_fp16.h>
#include <stdint.h>

#define NMAX 100000
#define EMAX 1600000

// ---------------- scratch (static device globals) ----------------
__device__ __align__(16) float  g_q  [(size_t)NMAX * 128];       // q plane fp32
__device__ __align__(16) __half g_kv [(size_t)2 * NMAX * 128];   // k plane | v plane fp16
__device__ __align__(16) float  g_agg[(size_t)NMAX * 128];
__device__ __align__(16) float  g_h  [(size_t)NMAX * 128];
__device__ __align__(16) float  g_hn [(size_t)NMAX * 128];
__device__ __align__(16) float  g_t2 [(size_t)NMAX * 64];
// CSR build
__device__ int    g_deg[NMAX];
__device__ int    g_rowptr[NMAX + 1];
__device__ int    g_cursor[NMAX];
__device__ int    g_esrc[EMAX];
__device__ __align__(8) float2 g_eea[EMAX];

__device__ __forceinline__ int clampi(int v, int hi) {
    return v < 0 ? 0 : (v >= hi ? hi - 1 : v);
}
// packed fp32x2 FMA (Blackwell)
__device__ __forceinline__ void ffma2(unsigned long long& c, unsigned long long a, unsigned long long b) {
    asm("fma.rn.f32x2 %0, %1, %2, %0;" : "+l"(c) : "l"(a), "l"(b));
}
__device__ __forceinline__ unsigned long long pack2(float x) {
    unsigned long long r;
    asm("mov.b64 %0, {%1, %1};" : "=l"(r) : "f"(x));
    return r;
}
__device__ __forceinline__ float2 unpack2(unsigned long long v) {
    float2 f;
    asm("mov.b64 {%0, %1}, %2;" : "=f"(f.x), "=f"(f.y) : "l"(v));
    return f;
}

// ---------------- CSR build ----------------
__global__ void zero_deg(int n) {
    int i = blockIdx.x * blockDim.x + threadIdx.x;
    if (i < n) g_deg[i] = 0;
}

__global__ void hist_kernel(const int* __restrict__ ei, int E, int n) {
    int e = blockIdx.x * blockDim.x + threadIdx.x;
    if (e < E) atomicAdd(&g_deg[clampi(ei[E + e], n)], 1);
}

// single-block chunked exclusive scan over g_deg -> g_rowptr, g_cursor
__global__ __launch_bounds__(1024)
void scan_kernel(int n) {
    __shared__ int sh[1024];
    int t = threadIdx.x;
    int chunk = (n + 1023) >> 10;
    int b = t * chunk;
    int e = min(n, b + chunk);
    int s = 0;
    for (int i = b; i < e; ++i) s += g_deg[i];
    sh[t] = s;
    __syncthreads();
    for (int off = 1; off < 1024; off <<= 1) {
        int v = (t >= off) ? sh[t - off] : 0;
        __syncthreads();
        sh[t] += v;
        __syncthreads();
    }
    int base = (t == 0) ? 0 : sh[t - 1];
    for (int i = b; i < e; ++i) {
        int d = g_deg[i];
        g_rowptr[i] = base;
        g_cursor[i] = base;
        base += d;
    }
    if (t == 1023) g_rowptr[n] = sh[1023];
}

__global__ void scatter_kernel(const int* __restrict__ ei, const float* __restrict__ ea,
                               int E, int n) {
    int e = blockIdx.x * blockDim.x + threadIdx.x;
    if (e >= E) return;
    int src = clampi(ei[e], n);
    int dst = clampi(ei[E + e], n);
    int pos = atomicAdd(&g_cursor[dst], 1);
    g_esrc[pos] = src;
    g_eea[pos]  = *reinterpret_cast<const float2*>(ea + (size_t)e * 2);
}

// ---------------- qkv sgemm: C=q fp32 plane, H=k/v fp16 planes ----------------
__global__ __launch_bounds__(256, 2)
void sgemm_qkv(const float* __restrict__ A, const float* __restrict__ B,
               float* __restrict__ Cq, __half* __restrict__ Hkv, int M)
{
    const int NCOLS = 384;
    __shared__ __align__(16) float As[8][128];
    __shared__ __align__(16) float Bs[8][128];

    const int t  = threadIdx.x;
    const int m0 = blockIdx.x * 128;
    const int n0 = blockIdx.y * 128;

    const int am = t >> 1;
    const int aq = (t & 1) * 4;
    const int brow = t >> 5;
    const int bcol = (t & 31) * 4;
    const int tx = t & 15;
    const int ty = t >> 4;

    int ar = m0 + am; if (ar >= M) ar = M - 1;
    const float* Ap = A + (size_t)ar * 128 + aq;
    const float* Bp = B + (size_t)brow * NCOLS + n0 + bcol;

    unsigned long long acc[8][4];
#pragma unroll
    for (int i = 0; i < 8; ++i)
#pragma unroll
        for (int j = 0; j < 4; ++j) acc[i][j] = 0ull;

    for (int k0 = 0; k0 < 128; k0 += 8) {
        float4 av = *reinterpret_cast<const float4*>(Ap + k0);
        As[aq + 0][am] = av.x;
        As[aq + 1][am] = av.y;
        As[aq + 2][am] = av.z;
        As[aq + 3][am] = av.w;
        *reinterpret_cast<float4*>(&Bs[brow][bcol]) =
            *reinterpret_cast<const float4*>(Bp + (size_t)k0 * NCOLS);
        __syncthreads();
#pragma unroll
        for (int kk = 0; kk < 8; ++kk) {
            const float* as = &As[kk][ty * 8];
            float4 a0 = *reinterpret_cast<const float4*>(as);
            float4 a1 = *reinterpret_cast<const float4*>(as + 4);
            const unsigned long long* bp =
                reinterpret_cast<const unsigned long long*>(&Bs[kk][tx * 8]);
            unsigned long long b0 = bp[0], b1 = bp[1], b2 = bp[2], b3 = bp[3];
            float aa[8] = {a0.x, a0.y, a0.z, a0.w, a1.x, a1.y, a1.z, a1.w};
#pragma unroll
            for (int i = 0; i < 8; ++i) {
                unsigned long long ap = pack2(aa[i]);
                ffma2(acc[i][0], ap, b0);
                ffma2(acc[i][1], ap, b1);
                ffma2(acc[i][2], ap, b2);
                ffma2(acc[i][3], ap, b3);
            }
        }
        __syncthreads();
    }

    const int colg = tx * 8;
    const int plane = n0 >> 7;   // 0=q, 1=k, 2=v

#pragma unroll
    for (int i = 0; i < 8; ++i) {
        int r = m0 + ty * 8 + i;
        if (r < M) {
            float c[8];
#pragma unroll
            for (int j = 0; j < 4; ++j) {
                float2 f = unpack2(acc[i][j]);
                c[2 * j] = f.x; c[2 * j + 1] = f.y;
            }
            if (plane == 0) {
                float* cp = Cq + (size_t)r * 128 + colg;
                float4 o0 = {c[0], c[1], c[2], c[3]};
                float4 o1 = {c[4], c[5], c[6], c[7]};
                *reinterpret_cast<float4*>(cp) = o0;
                *reinterpret_cast<float4*>(cp + 4) = o1;
            } else {
                __half2 h0 = __floats2half2_rn(c[0], c[1]);
                __half2 h1 = __floats2half2_rn(c[2], c[3]);
                __half2 h2 = __floats2half2_rn(c[4], c[5]);
                __half2 h3 = __floats2half2_rn(c[6], c[7]);
                uint4 u;
                u.x = *reinterpret_cast<unsigned*>(&h0);
                u.y = *reinterpret_cast<unsigned*>(&h1);
                u.z = *reinterpret_cast<unsigned*>(&h2);
                u.w = *reinterpret_cast<unsigned*>(&h3);
                __half* hp = Hkv + (size_t)(plane - 1) * M * 128 + (size_t)r * 128 + colg;
                *reinterpret_cast<uint4*>(hp) = u;
            }
        }
    }
}

// ---------------- generic fp32 sgemm (Wout path) ----------------
template<bool BIAS, bool RESID, bool RELU>
__global__ __launch_bounds__(256, 2)
void sgemm_f32x2(const float* __restrict__ A, const float* __restrict__ B,
                 const float* __restrict__ bias, const float* __restrict__ resid,
                 float* __restrict__ C, int M, int NCOLS)
{
    __shared__ __align__(16) float As[8][128];
    __shared__ __align__(16) float Bs[8][128];

    const int t  = threadIdx.x;
    const int m0 = blockIdx.x * 128;
    const int n0 = blockIdx.y * 128;

    const int am = t >> 1;
    const int aq = (t & 1) * 4;
    const int brow = t >> 5;
    const int bcol = (t & 31) * 4;
    const int tx = t & 15;
    const int ty = t >> 4;

    int ar = m0 + am; if (ar >= M) ar = M - 1;
    const float* Ap = A + (size_t)ar * 128 + aq;
    const float* Bp = B + (size_t)brow * NCOLS + n0 + bcol;

    unsigned long long acc[8][4];
#pragma unroll
    for (int i = 0; i < 8; ++i)
#pragma unroll
        for (int j = 0; j < 4; ++j) acc[i][j] = 0ull;

    for (int k0 = 0; k0 < 128; k0 += 8) {
        float4 av = *reinterpret_cast<const float4*>(Ap + k0);
        As[aq + 0][am] = av.x;
        As[aq + 1][am] = av.y;
        As[aq + 2][am] = av.z;
        As[aq + 3][am] = av.w;
        *reinterpret_cast<float4*>(&Bs[brow][bcol]) =
            *reinterpret_cast<const float4*>(Bp + (size_t)k0 * NCOLS);
        __syncthreads();
#pragma unroll
        for (int kk = 0; kk < 8; ++kk) {
            const float* as = &As[kk][ty * 8];
            float4 a0 = *reinterpret_cast<const float4*>(as);
            float4 a1 = *reinterpret_cast<const float4*>(as + 4);
            const unsigned long long* bp =
                reinterpret_cast<const unsigned long long*>(&Bs[kk][tx * 8]);
            unsigned long long b0 = bp[0], b1 = bp[1], b2 = bp[2], b3 = bp[3];
            float aa[8] = {a0.x, a0.y, a0.z, a0.w, a1.x, a1.y, a1.z, a1.w};
#pragma unroll
            for (int i = 0; i < 8; ++i) {
                unsigned long long ap = pack2(aa[i]);
                ffma2(acc[i][0], ap, b0);
                ffma2(acc[i][1], ap, b1);
                ffma2(acc[i][2], ap, b2);
                ffma2(acc[i][3], ap, b3);
            }
        }
        __syncthreads();
    }

    const int colg = tx * 8;
    float bb[8];
    if (BIAS) {
#pragma unroll
        for (int j = 0; j < 8; ++j) bb[j] = bias[n0 + colg + j];
    }

#pragma unroll
    for (int i = 0; i < 8; ++i) {
        int r = m0 + ty * 8 + i;
        if (r < M) {
            float c[8];
#pragma unroll
            for (int j = 0; j < 4; ++j) {
                float2 f = unpack2(acc[i][j]);
                c[2 * j] = f.x; c[2 * j + 1] = f.y;
            }
            if (BIAS) {
#pragma unroll
                for (int j = 0; j < 8; ++j) c[j] += bb[j];
            }
            if (RESID) {
                const float* rp = resid + (size_t)r * 128 + n0 + colg;
                float4 r0 = *reinterpret_cast<const float4*>(rp);
                float4 r1 = *reinterpret_cast<const float4*>(rp + 4);
                c[0] += r0.x; c[1] += r0.y; c[2] += r0.z; c[3] += r0.w;
                c[4] += r1.x; c[5] += r1.y; c[6] += r1.z; c[7] += r1.w;
            }
            if (RELU) {
#pragma unroll
                for (int j = 0; j < 8; ++j) c[j] = fmaxf(c[j], 0.f);
            }
            float* cp = C + (size_t)r * NCOLS + n0 + colg;
            float4 o0 = {c[0], c[1], c[2], c[3]};
            float4 o1 = {c[4], c[5], c[6], c[7]};
            *reinterpret_cast<float4*>(cp) = o0;
            *reinterpret_cast<float4*>(cp + 4) = o1;
        }
    }
}

// ---------------- small sgemm (64-wide tiles) for Wc1 ----------------
template<int NCOLS, bool BIAS, bool RELU>
__global__ __launch_bounds__(256)
void sgemm_k128s(const float* __restrict__ A, const float* __restrict__ B,
                 const float* __restrict__ bias, float* __restrict__ C, int M)
{
    __shared__ __align__(16) float As[16][64];
    __shared__ __align__(16) float Bs[16][64];

    const int t  = threadIdx.x;
    const int m0 = blockIdx.x * 64;
    const int n0 = blockIdx.y * 64;
    const int tx = t & 15;
    const int ty = t >> 4;
    const int arow = t >> 2;
    const int acol = (t & 3) << 2;
    const int brow = t >> 4;
    const int bcol = (t & 15) << 2;

    int ar = m0 + arow; if (ar >= M) ar = M - 1;
    const float* Ap = A + (size_t)ar * 128 + acol;
    const float* Bp = B + (size_t)brow * NCOLS + n0 + bcol;

    float4 acc0 = {0,0,0,0}, acc1 = {0,0,0,0}, acc2 = {0,0,0,0}, acc3 = {0,0,0,0};

    for (int k0 = 0; k0 < 128; k0 += 16) {
        float4 av = *reinterpret_cast<const float4*>(Ap + k0);
        As[acol + 0][arow] = av.x;
        As[acol + 1][arow] = av.y;
        As[acol + 2][arow] = av.z;
        As[acol + 3][arow] = av.w;
        *reinterpret_cast<float4*>(&Bs[brow][bcol]) =
            *reinterpret_cast<const float4*>(Bp + (size_t)k0 * NCOLS);
        __syncthreads();
#pragma unroll
        for (int kk = 0; kk < 16; ++kk) {
            float4 a = *reinterpret_cast<const float4*>(&As[kk][ty << 2]);
            float4 b = *reinterpret_cast<const float4*>(&Bs[kk][tx << 2]);
            acc0.x += a.x * b.x; acc0.y += a.x * b.y; acc0.z += a.x * b.z; acc0.w += a.x * b.w;
            acc1.x += a.y * b.x; acc1.y += a.y * b.y; acc1.z += a.y * b.z; acc1.w += a.y * b.w;
            acc2.x += a.z * b.x; acc2.y += a.z * b.y; acc2.z += a.z * b.z; acc2.w += a.z * b.w;
            acc3.x += a.w * b.x; acc3.y += a.w * b.y; acc3.z += a.w * b.z; acc3.w += a.w * b.w;
        }
        __syncthreads();
    }

    const int ocol = n0 + (tx << 2);
    float4 bb = {0,0,0,0};
    if (BIAS) bb = *reinterpret_cast<const float4*>(bias + ocol);

    float4 accs[4] = {acc0, acc1, acc2, acc3};
#pragma unroll
    for (int i = 0; i < 4; ++i) {
        int r = m0 + (ty << 2) + i;
        if (r < M) {
            float4 o = accs[i];
            if (BIAS) { o.x += bb.x; o.y += bb.y; o.z += bb.z; o.w += bb.w; }
            if (RELU) {
                o.x = fmaxf(o.x, 0.f); o.y = fmaxf(o.y, 0.f);
                o.z = fmaxf(o.z, 0.f); o.w = fmaxf(o.w, 0.f);
            }
            *reinterpret_cast<float4*>(C + (size_t)r * NCOLS + ocol) = o;
        }
    }
}

// ---------------- fused CSR attention: one warp per node ----------------
// agg[i] = sum_e exp(s_e) * v[src_e] / sum_e exp(s_e)
__global__ __launch_bounds__(128)
void fused_attn(const float* __restrict__ Wedge, int n)
{
    int i    = (blockIdx.x * blockDim.x + threadIdx.x) >> 5;
    int lane = threadIdx.x & 31;
    if (i >= n) return;
    int hg = lane >> 2;

    int beg = g_rowptr[i];
    int end = g_rowptr[i + 1];

    float4 q4 = *reinterpret_cast<const float4*>(g_q + (size_t)i * 128 + lane * 4);
    q4.x *= 0.25f; q4.y *= 0.25f; q4.z *= 0.25f; q4.w *= 0.25f;   // scale = D^-0.5
    float w0 = Wedge[hg], w1 = Wedge[8 + hg];

    const __half* kplane = g_kv;
    const __half* vplane = g_kv + (size_t)n * 128;

    float4 accv = {0.f, 0.f, 0.f, 0.f};
    float  accd = 0.f;

    for (int j = beg; j < end; j += 4) {
        int    idx[4];
        float2 eav[4];
#pragma unroll
        for (int u = 0; u < 4; ++u) {
            int jj = min(j + u, end - 1);
            idx[u] = g_esrc[jj];
            eav[u] = g_eea[jj];
        }
        uint2 kraw[4], vraw[4];
#pragma unroll
        for (int u = 0; u < 4; ++u) {
            kraw[u] = *reinterpret_cast<const uint2*>(kplane + (size_t)idx[u] * 128 + lane * 4);
            vraw[u] = *reinterpret_cast<const uint2*>(vplane + (size_t)idx[u] * 128 + lane * 4);
        }
#pragma unroll
        for (int u = 0; u < 4; ++u) {
            float2 ka = __half22float2(*reinterpret_cast<const __half2*>(&kraw[u].x));
            float2 kb = __half22float2(*reinterpret_cast<const __half2*>(&kraw[u].y));
            float p = q4.x * ka.x + q4.y * ka.y + q4.z * kb.x + q4.w * kb.y;
            p += __shfl_xor_sync(0xffffffffu, p, 1);
            p += __shfl_xor_sync(0xffffffffu, p, 2);

            float s  = p + eav[u].x * w0 + eav[u].y * w1;
            float ex = __expf(s);
            if (j + u >= end) ex = 0.f;

            float2 va = __half22float2(*reinterpret_cast<const __half2*>(&vraw[u].x));
            float2 vb = __half22float2(*reinterpret_cast<const __half2*>(&vraw[u].y));
            accv.x += ex * va.x;
            accv.y += ex * va.y;
            accv.z += ex * vb.x;
            accv.w += ex * vb.y;
            accd   += ex;
        }
    }

    float invd = __fdividef(1.f, accd + 1e-16f);
    float4 o = {accv.x * invd, accv.y * invd, accv.z * invd, accv.w * invd};
    *reinterpret_cast<float4*>(g_agg + (size_t)i * 128 + lane * 4) = o;
}

// ---------------- layernorm ----------------
__global__ __launch_bounds__(256)
void ln_kernel(const float* __restrict__ lw, const float* __restrict__ lb, int n)
{
    int node = (blockIdx.x * blockDim.x + threadIdx.x) >> 5;
    int lane = threadIdx.x & 31;
    if (node >= n) return;

    float4 v = *reinterpret_cast<const float4*>(g_h + (size_t)node * 128 + lane * 4);
    float s = v.x + v.y + v.z + v.w;
    float q = v.x * v.x + v.y * v.y + v.z * v.z + v.w * v.w;
#pragma unroll
    for (int o = 16; o; o >>= 1) {
        s += __shfl_xor_sync(0xffffffffu, s, o);
        q += __shfl_xor_sync(0xffffffffu, q, o);
    }
    float mu  = s * (1.f / 128.f);
    float var = q * (1.f / 128.f) - mu * mu;
    float rs  = rsqrtf(var + 1e-5f);
    float4 w4 = *reinterpret_cast<const float4*>(lw + lane * 4);
    float4 b4 = *reinterpret_cast<const float4*>(lb + lane * 4);
    float4 o;
    o.x = (v.x - mu) * rs * w4.x + b4.x;
    o.y = (v.y - mu) * rs * w4.y + b4.y;
    o.z = (v.z - mu) * rs * w4.z + b4.z;
    o.w = (v.w - mu) * rs * w4.w + b4.w;
    *reinterpret_cast<float4*>(g_hn + (size_t)node * 128 + lane * 4) = o;
}

// ---------------- final: out[N,3] = t2[N,64] @ Wc2[64,3] + bc2 ----------------
__global__ __launch_bounds__(256)
void final_kernel(const float* __restrict__ Wc2, const float* __restrict__ bc2,
                  float* __restrict__ out, int n)
{
    int node = (blockIdx.x * blockDim.x + threadIdx.x) >> 5;
    int lane = threadIdx.x & 31;
    if (node >= n) return;

    float2 tv = *reinterpret_cast<const float2*>(g_t2 + (size_t)node * 64 + lane * 2);
    int k0 = lane * 2;
    float s0 = tv.x * Wc2[k0 * 3 + 0] + tv.y * Wc2[k0 * 3 + 3];
    float s1 = tv.x * Wc2[k0 * 3 + 1] + tv.y * Wc2[k0 * 3 + 4];
    float s2 = tv.x * Wc2[k0 * 3 + 2] + tv.y * Wc2[k0 * 3 + 5];
#pragma unroll
    for (int o = 16; o; o >>= 1) {
        s0 += __shfl_xor_sync(0xffffffffu, s0, o);
        s1 += __shfl_xor_sync(0xffffffffu, s1, o);
        s2 += __shfl_xor_sync(0xffffffffu, s2, o);
    }
    if (lane == 0) {
        out[(size_t)node * 3 + 0] = s0 + bc2[0];
        out[(size_t)node * 3 + 1] = s1 + bc2[1];
        out[(size_t)node * 3 + 2] = s2 + bc2[2];
    }
}

// ---------------- launch ----------------
extern "C" void kernel_launch(void* const* d_in, const int* in_sizes, int n_in,
                              void* d_out, int out_size)
{
    const float* x     = (const float*)d_in[0];
    const int*   ei    = (const int*)d_in[1];
    const float* ea    = (const float*)d_in[2];
    const float* Wqkv  = (const float*)d_in[3];
    const float* Wedge = (const float*)d_in[4];
    const float* Wout  = (const float*)d_in[5];
    const float* bout  = (const float*)d_in[6];
    const float* lnw   = (const float*)d_in[7];
    const float* lnb   = (const float*)d_in[8];
    const float* Wc1   = (const float*)d_in[9];
    const float* bc1   = (const float*)d_in[10];
    const float* Wc2   = (const float*)d_in[11];
    const float* bc2   = (const float*)d_in[12];
    float* out = (float*)d_out;

    const int n = in_sizes[0] / 128;
    const int E = in_sizes[1] / 2;

    float *q, *agg, *h, *hn, *t2;
    __half* kv;
    cudaGetSymbolAddress((void**)&q,   g_q);
    cudaGetSymbolAddress((void**)&kv,  g_kv);
    cudaGetSymbolAddress((void**)&agg, g_agg);
    cudaGetSymbolAddress((void**)&h,   g_h);
    cudaGetSymbolAddress((void**)&hn,  g_hn);
    cudaGetSymbolAddress((void**)&t2,  g_t2);

    // CSR build (overlaps conceptually with qkv GEMM work; serialized on one stream)
    zero_deg<<<(n + 255) / 256, 256>>>(n);
    hist_kernel<<<(E + 255) / 256, 256>>>(ei, E, n);
    scan_kernel<<<1, 1024>>>(n);
    scatter_kernel<<<(E + 255) / 256, 256>>>(ei, ea, E, n);

    // qkv = x @ Wqkv -> q fp32 plane + k/v fp16 planes
    sgemm_qkv<<<dim3((n + 127) / 128, 3), 256>>>(x, Wqkv, q, kv, n);

    // fused per-node attention
    fused_attn<<<(n + 3) / 4, 128>>>(Wedge, n);

    // h = agg @ Wout + bout + x
    sgemm_f32x2<true, true, false>
        <<<dim3((n + 127) / 128, 1), 256>>>(agg, Wout, bout, x, h, n, 128);

    // layernorm
    ln_kernel<<<(n + 7) / 8, 256>>>(lnw, lnb, n);

    // t2 = relu(hn @ Wc1 + bc1)
    sgemm_k128s<64, true, true>
        <<<dim3((n + 63) / 64, 1), 256>>>(hn, Wc1, bc1, t2, n);

    // out = t2 @ Wc2 + bc2
    final_kernel<<<(n + 7) / 8, 256>>>(Wc2, bc2, out, n);
}

// round 6
// speedup vs baseline: 1.8072x; 1.3443x over previous
#include <cuda_runtime.h>
#include <cuda_fp16.h>
#include <stdint.h>

#define NMAX 100000
#define EMAX 1600000

// ---------------- scratch (static device globals) ----------------
__device__ __align__(16) float  g_q  [(size_t)NMAX * 128];
__device__ __align__(16) __half g_kv [(size_t)2 * NMAX * 128];   // k | v planes fp16
__device__ __align__(16) float  g_agg[(size_t)NMAX * 128];
__device__ __align__(16) float  g_h  [(size_t)NMAX * 128];
__device__ __align__(16) float  g_hn [(size_t)NMAX * 128];
__device__ __align__(16) float  g_t2 [(size_t)NMAX * 64];
// CSR
__device__ int    g_deg[NMAX];
__device__ int    g_rowptr[NMAX + 1];
__device__ int    g_cursor[NMAX];
__device__ int    g_esrc[EMAX];
__device__ __align__(8) float2 g_eea[EMAX];

__device__ __forceinline__ int clampi(int v, int hi) {
    return v < 0 ? 0 : (v >= hi ? hi - 1 : v);
}
__device__ __forceinline__ uint32_t f2tf32(float f) {
    uint32_t u;
    asm("cvt.rna.tf32.f32 %0, %1;" : "=r"(u) : "f"(f));
    return u;
}
__device__ __forceinline__ void mma_tf32(float4& c, const uint32_t a[4], const uint32_t b[2]) {
    asm("mma.sync.aligned.m16n8k8.row.col.f32.tf32.tf32.f32 "
        "{%0,%1,%2,%3}, {%4,%5,%6,%7}, {%8,%9}, {%0,%1,%2,%3};"
        : "+f"(c.x), "+f"(c.y), "+f"(c.z), "+f"(c.w)
        : "r"(a[0]), "r"(a[1]), "r"(a[2]), "r"(a[3]), "r"(b[0]), "r"(b[1]));
}

// ---------------- CSR build ----------------
__global__ void zero_deg(int n) {
    int i = blockIdx.x * blockDim.x + threadIdx.x;
    if (i < n) g_deg[i] = 0;
}
__global__ void hist_kernel(const int* __restrict__ ei, int E, int n) {
    int e = blockIdx.x * blockDim.x + threadIdx.x;
    if (e < E) atomicAdd(&g_deg[clampi(ei[E + e], n)], 1);
}
__global__ __launch_bounds__(1024)
void scan_kernel(int n) {
    __shared__ int sh[1024];
    int t = threadIdx.x;
    int chunk = (n + 1023) >> 10;
    int b = t * chunk;
    int e = min(n, b + chunk);
    int s = 0;
    for (int i = b; i < e; ++i) s += g_deg[i];
    sh[t] = s;
    __syncthreads();
    for (int off = 1; off < 1024; off <<= 1) {
        int v = (t >= off) ? sh[t - off] : 0;
        __syncthreads();
        sh[t] += v;
        __syncthreads();
    }
    int base = (t == 0) ? 0 : sh[t - 1];
    for (int i = b; i < e; ++i) {
        int d = g_deg[i];
        g_rowptr[i] = base;
        g_cursor[i] = base;
        base += d;
    }
    if (t == 1023) g_rowptr[n] = sh[1023];
}
__global__ void scatter_kernel(const int* __restrict__ ei, const float* __restrict__ ea,
                               int E, int n) {
    int e = blockIdx.x * blockDim.x + threadIdx.x;
    if (e >= E) return;
    int src = clampi(ei[e], n);
    int dst = clampi(ei[E + e], n);
    int pos = atomicAdd(&g_cursor[dst], 1);
    g_esrc[pos] = src;
    g_eea[pos]  = *reinterpret_cast<const float2*>(ea + (size_t)e * 2);
}

// ---------------- tf32 tensor-core GEMM, K=128, M-tile=128, N-tile=NT ----------------
// EPI 0: qkv split -> q fp32 plane + k/v fp16 planes (NCOLS=384)
// EPI 1: bias + resid -> C (NCOLS=128)
// EPI 2: bias + relu  -> C (NCOLS=64, NT=64)
template<int NT, int EPI>
__global__ __launch_bounds__(256)
void gemm_tf32(const float* __restrict__ A, const float* __restrict__ B,
               const float* __restrict__ bias, const float* __restrict__ resid,
               float* __restrict__ C, __half* __restrict__ Hkv, int M, int NCOLS)
{
    constexpr int WM = (NT == 128) ? 2 : 4;   // warps along M
    constexpr int WN = 8 / WM;                // warps along N
    constexpr int MFRAG = 8 / WM;             // m16 frags per warp
    constexpr int NFRAG = NT / (WN * 8);      // n8 frags per warp (=4)

    __shared__ uint32_t As[128][20];          // [m][k], pitch 20 -> conflict-free frags
    __shared__ uint32_t Bs[16][NT + 8];       // [k][n], pitch%32==8 -> conflict-free

    const int t = threadIdx.x;
    const int lane = t & 31;
    const int wid  = t >> 5;
    const int warp_m = wid / WN;
    const int warp_n = wid % WN;
    const int m0 = blockIdx.x * 128;
    const int n0 = blockIdx.y * NT;
    const int lr = lane >> 2, lc = lane & 3;

    float4 acc[MFRAG][NFRAG];
#pragma unroll
    for (int i = 0; i < MFRAG; ++i)
#pragma unroll
        for (int j = 0; j < NFRAG; ++j) acc[i][j] = make_float4(0.f, 0.f, 0.f, 0.f);

    const int arow = t >> 1;
    const int acb  = (t & 1) * 8;
    int agr = m0 + arow; if (agr >= M) agr = M - 1;
    const float* Ap = A + (size_t)agr * 128 + acb;

    const int brow = t >> 4;
    const int bcb  = (t & 15) * (NT / 16);
    const float* Bp = B + (size_t)brow * NCOLS + n0 + bcb;

    for (int k0 = 0; k0 < 128; k0 += 16) {
        float4 av0 = *reinterpret_cast<const float4*>(Ap + k0);
        float4 av1 = *reinterpret_cast<const float4*>(Ap + k0 + 4);
        As[arow][acb + 0] = f2tf32(av0.x); As[arow][acb + 1] = f2tf32(av0.y);
        As[arow][acb + 2] = f2tf32(av0.z); As[arow][acb + 3] = f2tf32(av0.w);
        As[arow][acb + 4] = f2tf32(av1.x); As[arow][acb + 5] = f2tf32(av1.y);
        As[arow][acb + 6] = f2tf32(av1.z); As[arow][acb + 7] = f2tf32(av1.w);
#pragma unroll
        for (int j = 0; j < NT / 64; ++j) {
            float4 bv = *reinterpret_cast<const float4*>(Bp + (size_t)k0 * NCOLS + j * 4);
            Bs[brow][bcb + j * 4 + 0] = f2tf32(bv.x);
            Bs[brow][bcb + j * 4 + 1] = f2tf32(bv.y);
            Bs[brow][bcb + j * 4 + 2] = f2tf32(bv.z);
            Bs[brow][bcb + j * 4 + 3] = f2tf32(bv.w);
        }
        __syncthreads();

#pragma unroll
        for (int ks = 0; ks < 16; ks += 8) {
            uint32_t afr[MFRAG][4];
#pragma unroll
            for (int fm = 0; fm < MFRAG; ++fm) {
                int mr = warp_m * (MFRAG * 16) + fm * 16 + lr;
                afr[fm][0] = As[mr][ks + lc];
                afr[fm][1] = As[mr + 8][ks + lc];
                afr[fm][2] = As[mr][ks + lc + 4];
                afr[fm][3] = As[mr + 8][ks + lc + 4];
            }
            uint32_t bfr[NFRAG][2];
#pragma unroll
            for (int fn = 0; fn < NFRAG; ++fn) {
                int nc = warp_n * (NFRAG * 8) + fn * 8 + lr;
                bfr[fn][0] = Bs[ks + lc][nc];
                bfr[fn][1] = Bs[ks + lc + 4][nc];
            }
#pragma unroll
            for (int fm = 0; fm < MFRAG; ++fm)
#pragma unroll
                for (int fn = 0; fn < NFRAG; ++fn)
                    mma_tf32(acc[fm][fn], afr[fm], bfr[fn]);
        }
        __syncthreads();
    }

    // ---------------- epilogue ----------------
    const int plane = n0 >> 7;   // for EPI 0
#pragma unroll
    for (int fm = 0; fm < MFRAG; ++fm) {
        int r0 = m0 + warp_m * (MFRAG * 16) + fm * 16 + lr;
        int r1 = r0 + 8;
#pragma unroll
        for (int fn = 0; fn < NFRAG; ++fn) {
            int cl = warp_n * (NFRAG * 8) + fn * 8 + 2 * lc;    // local col in tile
            float4 c = acc[fm][fn];
            if (EPI == 0) {
                if (plane == 0) {
                    if (r0 < M) *reinterpret_cast<float2*>(C + (size_t)r0 * 128 + cl) = make_float2(c.x, c.y);
                    if (r1 < M) *reinterpret_cast<float2*>(C + (size_t)r1 * 128 + cl) = make_float2(c.z, c.w);
                } else {
                    __half* hp = Hkv + (size_t)(plane - 1) * M * 128;
                    if (r0 < M) *reinterpret_cast<__half2*>(hp + (size_t)r0 * 128 + cl) = __floats2half2_rn(c.x, c.y);
                    if (r1 < M) *reinterpret_cast<__half2*>(hp + (size_t)r1 * 128 + cl) = __floats2half2_rn(c.z, c.w);
                }
            } else {
                int col = n0 + cl;
                float b0 = bias[col], b1 = bias[col + 1];
                if (EPI == 1) {
                    if (r0 < M) {
                        float2 rr = *reinterpret_cast<const float2*>(resid + (size_t)r0 * NCOLS + col);
                        *reinterpret_cast<float2*>(C + (size_t)r0 * NCOLS + col) =
                            make_float2(c.x + b0 + rr.x, c.y + b1 + rr.y);
                    }
                    if (r1 < M) {
                        float2 rr = *reinterpret_cast<const float2*>(resid + (size_t)r1 * NCOLS + col);
                        *reinterpret_cast<float2*>(C + (size_t)r1 * NCOLS + col) =
                            make_float2(c.z + b0 + rr.x, c.w + b1 + rr.y);
                    }
                } else {
                    if (r0 < M)
                        *reinterpret_cast<float2*>(C + (size_t)r0 * NCOLS + col) =
                            make_float2(fmaxf(c.x + b0, 0.f), fmaxf(c.y + b1, 0.f));
                    if (r1 < M)
                        *reinterpret_cast<float2*>(C + (size_t)r1 * NCOLS + col) =
                            make_float2(fmaxf(c.z + b0, 0.f), fmaxf(c.w + b1, 0.f));
                }
            }
        }
    }
}

// ---------------- fused CSR attention: one warp per node, 8-edge batches ----------------
__global__ __launch_bounds__(128)
void fused_attn(const float* __restrict__ Wedge, int n)
{
    int i    = (blockIdx.x * blockDim.x + threadIdx.x) >> 5;
    int lane = threadIdx.x & 31;
    if (i >= n) return;
    int hg = lane >> 2;

    int beg = g_rowptr[i];
    int end = g_rowptr[i + 1];

    float4 q4 = *reinterpret_cast<const float4*>(g_q + (size_t)i * 128 + lane * 4);
    q4.x *= 0.25f; q4.y *= 0.25f; q4.z *= 0.25f; q4.w *= 0.25f;
    float w0 = Wedge[hg], w1 = Wedge[8 + hg];

    const __half* kplane = g_kv;
    const __half* vplane = g_kv + (size_t)n * 128;

    float4 accv = {0.f, 0.f, 0.f, 0.f};
    float  accd = 0.f;

    for (int j = beg; j < end; j += 8) {
        int    idx[8];
        float2 eav[8];
#pragma unroll
        for (int u = 0; u < 8; ++u) {
            int jj = min(j + u, end - 1);
            idx[u] = g_esrc[jj];
            eav[u] = g_eea[jj];
        }
        uint2 kraw[8];
#pragma unroll
        for (int u = 0; u < 8; ++u)
            kraw[u] = *reinterpret_cast<const uint2*>(kplane + (size_t)idx[u] * 128 + lane * 4);
        uint2 vraw[8];
#pragma unroll
        for (int u = 0; u < 8; ++u)
            vraw[u] = *reinterpret_cast<const uint2*>(vplane + (size_t)idx[u] * 128 + lane * 4);

        float ex[8];
#pragma unroll
        for (int u = 0; u < 8; ++u) {
            float2 ka = __half22float2(*reinterpret_cast<const __half2*>(&kraw[u].x));
            float2 kb = __half22float2(*reinterpret_cast<const __half2*>(&kraw[u].y));
            float p = q4.x * ka.x + q4.y * ka.y + q4.z * kb.x + q4.w * kb.y;
            p += __shfl_xor_sync(0xffffffffu, p, 1);
            p += __shfl_xor_sync(0xffffffffu, p, 2);
            float s = p + eav[u].x * w0 + eav[u].y * w1;
            float e = __expf(s);
            ex[u] = (j + u < end) ? e : 0.f;
            accd += ex[u];
        }
#pragma unroll
        for (int u = 0; u < 8; ++u) {
            float2 va = __half22float2(*reinterpret_cast<const __half2*>(&vraw[u].x));
            float2 vb = __half22float2(*reinterpret_cast<const __half2*>(&vraw[u].y));
            accv.x += ex[u] * va.x;
            accv.y += ex[u] * va.y;
            accv.z += ex[u] * vb.x;
            accv.w += ex[u] * vb.y;
        }
    }

    float invd = __fdividef(1.f, accd + 1e-16f);
    float4 o = {accv.x * invd, accv.y * invd, accv.z * invd, accv.w * invd};
    *reinterpret_cast<float4*>(g_agg + (size_t)i * 128 + lane * 4) = o;
}

// ---------------- layernorm ----------------
__global__ __launch_bounds__(256)
void ln_kernel(const float* __restrict__ lw, const float* __restrict__ lb, int n)
{
    int node = (blockIdx.x * blockDim.x + threadIdx.x) >> 5;
    int lane = threadIdx.x & 31;
    if (node >= n) return;

    float4 v = *reinterpret_cast<const float4*>(g_h + (size_t)node * 128 + lane * 4);
    float s = v.x + v.y + v.z + v.w;
    float q = v.x * v.x + v.y * v.y + v.z * v.z + v.w * v.w;
#pragma unroll
    for (int o = 16; o; o >>= 1) {
        s += __shfl_xor_sync(0xffffffffu, s, o);
        q += __shfl_xor_sync(0xffffffffu, q, o);
    }
    float mu  = s * (1.f / 128.f);
    float var = q * (1.f / 128.f) - mu * mu;
    float rs  = rsqrtf(var + 1e-5f);
    float4 w4 = *reinterpret_cast<const float4*>(lw + lane * 4);
    float4 b4 = *reinterpret_cast<const float4*>(lb + lane * 4);
    float4 o;
    o.x = (v.x - mu) * rs * w4.x + b4.x;
    o.y = (v.y - mu) * rs * w4.y + b4.y;
    o.z = (v.z - mu) * rs * w4.z + b4.z;
    o.w = (v.w - mu) * rs * w4.w + b4.w;
    *reinterpret_cast<float4*>(g_hn + (size_t)node * 128 + lane * 4) = o;
}

// ---------------- final: out[N,3] = t2[N,64] @ Wc2[64,3] + bc2 ----------------
__global__ __launch_bounds__(256)
void final_kernel(const float* __restrict__ Wc2, const float* __restrict__ bc2,
                  float* __restrict__ out, int n)
{
    int node = (blockIdx.x * blockDim.x + threadIdx.x) >> 5;
    int lane = threadIdx.x & 31;
    if (node >= n) return;

    float2 tv = *reinterpret_cast<const float2*>(g_t2 + (size_t)node * 64 + lane * 2);
    int k0 = lane * 2;
    float s0 = tv.x * Wc2[k0 * 3 + 0] + tv.y * Wc2[k0 * 3 + 3];
    float s1 = tv.x * Wc2[k0 * 3 + 1] + tv.y * Wc2[k0 * 3 + 4];
    float s2 = tv.x * Wc2[k0 * 3 + 2] + tv.y * Wc2[k0 * 3 + 5];
#pragma unroll
    for (int o = 16; o; o >>= 1) {
        s0 += __shfl_xor_sync(0xffffffffu, s0, o);
        s1 += __shfl_xor_sync(0xffffffffu, s1, o);
        s2 += __shfl_xor_sync(0xffffffffu, s2, o);
    }
    if (lane == 0) {
        out[(size_t)node * 3 + 0] = s0 + bc2[0];
        out[(size_t)node * 3 + 1] = s1 + bc2[1];
        out[(size_t)node * 3 + 2] = s2 + bc2[2];
    }
}

// ---------------- launch ----------------
extern "C" void kernel_launch(void* const* d_in, const int* in_sizes, int n_in,
                              void* d_out, int out_size)
{
    const float* x     = (const float*)d_in[0];
    const int*   ei    = (const int*)d_in[1];
    const float* ea    = (const float*)d_in[2];
    const float* Wqkv  = (const float*)d_in[3];
    const float* Wedge = (const float*)d_in[4];
    const float* Wout  = (const float*)d_in[5];
    const float* bout  = (const float*)d_in[6];
    const float* lnw   = (const float*)d_in[7];
    const float* lnb   = (const float*)d_in[8];
    const float* Wc1   = (const float*)d_in[9];
    const float* bc1   = (const float*)d_in[10];
    const float* Wc2   = (const float*)d_in[11];
    const float* bc2   = (const float*)d_in[12];
    float* out = (float*)d_out;

    const int n = in_sizes[0] / 128;
    const int E = in_sizes[1] / 2;

    float *q, *agg, *h, *hn, *t2;
    __half* kv;
    cudaGetSymbolAddress((void**)&q,   g_q);
    cudaGetSymbolAddress((void**)&kv,  g_kv);
    cudaGetSymbolAddress((void**)&agg, g_agg);
    cudaGetSymbolAddress((void**)&h,   g_h);
    cudaGetSymbolAddress((void**)&hn,  g_hn);
    cudaGetSymbolAddress((void**)&t2,  g_t2);

    // CSR build
    zero_deg<<<(n + 255) / 256, 256>>>(n);
    hist_kernel<<<(E + 255) / 256, 256>>>(ei, E, n);
    scan_kernel<<<1, 1024>>>(n);
    scatter_kernel<<<(E + 255) / 256, 256>>>(ei, ea, E, n);

    // qkv = x @ Wqkv -> q fp32 + k/v fp16 planes   (tf32 tensor cores)
    gemm_tf32<128, 0><<<dim3((n + 127) / 128, 3), 256>>>(
        x, Wqkv, nullptr, nullptr, q, kv, n, 384);

    // fused per-node attention
    fused_attn<<<(n + 3) / 4, 128>>>(Wedge, n);

    // h = agg @ Wout + bout + x
    gemm_tf32<128, 1><<<dim3((n + 127) / 128, 1), 256>>>(
        agg, Wout, bout, x, h, nullptr, n, 128);

    // layernorm
    ln_kernel<<<(n + 7) / 8, 256>>>(lnw, lnb, n);

    // t2 = relu(hn @ Wc1 + bc1)
    gemm_tf32<64, 2><<<dim3((n + 127) / 128, 1), 256>>>(
        hn, Wc1, bc1, nullptr, t2, nullptr, n, 64);

    // out = t2 @ Wc2 + bc2
    final_kernel<<<(n + 7) / 8, 256>>>(Wc2, bc2, out, n);
}